// round 3
// baseline (speedup 1.0000x reference)
#include <cuda_runtime.h>
#include <math.h>

#define K_DIM   1024
#define S_LEN   2048
#define BATCH   2
#define NHEADS  16
#define HDIM    64
#define BH      (BATCH*NHEADS)

// Scratch (device globals: no allocation allowed)
__device__ float g_q[BH * S_LEN * HDIM];
__device__ float g_k[BH * S_LEN * HDIM];
__device__ float g_v[BH * S_LEN * HDIM];
__device__ float g_attn[BATCH * S_LEN * K_DIM];

// ---------------------------------------------------------------------------
// NT GEMM: C[m,n] = sum_k A[m,k] * W[n,k] + bias[n]
// mode 0: write C row-major (M x N)
// mode 1: QKV scatter into g_q/g_k/g_v with [b,h,s,d] layout
// Tiles: 64x64x64, 256 threads, 4x4 microtile, rows/cols mapped as t+16*i
// ---------------------------------------------------------------------------
__global__ __launch_bounds__(256) void gemm_nt_kernel(
    const float* __restrict__ A, const float* __restrict__ W,
    const float* __restrict__ bias, float* __restrict__ C,
    int N, int mode)
{
    __shared__ float As[64][68];
    __shared__ float Bs[64][68];
    const int tid = threadIdx.x;
    const int ty = tid >> 4;     // 0..15
    const int tx = tid & 15;     // 0..15
    const int mbase = blockIdx.y * 64;
    const int nbase = blockIdx.x * 64;

    float acc[4][4] = {};

    for (int kt = 0; kt < K_DIM / 64; kt++) {
#pragma unroll
        for (int r = 0; r < 4; r++) {
            int idx = tid + 256 * r;              // 0..1023 float4 slots
            int row = idx >> 4;
            int c4  = (idx & 15) * 4;
            *(float4*)&As[row][c4] =
                *(const float4*)&A[(size_t)(mbase + row) * K_DIM + kt * 64 + c4];
            *(float4*)&Bs[row][c4] =
                *(const float4*)&W[(size_t)(nbase + row) * K_DIM + kt * 64 + c4];
        }
        __syncthreads();

#pragma unroll
        for (int kk = 0; kk < 64; kk += 4) {
            float4 a4[4], b4[4];
#pragma unroll
            for (int i = 0; i < 4; i++) a4[i] = *(const float4*)&As[ty + 16 * i][kk];
#pragma unroll
            for (int j = 0; j < 4; j++) b4[j] = *(const float4*)&Bs[tx + 16 * j][kk];
#pragma unroll
            for (int i = 0; i < 4; i++)
#pragma unroll
                for (int j = 0; j < 4; j++) {
                    acc[i][j] += a4[i].x * b4[j].x + a4[i].y * b4[j].y
                               + a4[i].z * b4[j].z + a4[i].w * b4[j].w;
                }
        }
        __syncthreads();
    }

#pragma unroll
    for (int i = 0; i < 4; i++) {
        int m = mbase + ty + 16 * i;
#pragma unroll
        for (int j = 0; j < 4; j++) {
            int n = nbase + tx + 16 * j;
            float v = acc[i][j] + bias[n];
            if (mode == 0) {
                C[(size_t)m * N + n] = v;
            } else {
                int part = n >> 10;          // 0=q 1=k 2=v
                int nn = n & 1023;
                int h = nn >> 6;
                int d = nn & 63;
                int b = m >> 11;             // /2048
                int s = m & 2047;
                float* buf = (part == 0) ? g_q : (part == 1) ? g_k : g_v;
                buf[(((size_t)(b * NHEADS + h)) * S_LEN + s) * HDIM + d] = v;
            }
        }
    }
}

// ---------------------------------------------------------------------------
// Flash-style ALiBi attention. grid = (S/64 qtiles, B*H). 256 threads.
// Per key tile: S = Q K^T (64x64x64), online softmax w/ ALiBi bias, O += P V.
// V stored transposed in smem so both GEMMs are contiguous-K.
// Mask is read as 32-bit words (nonzero == attend): works for both int32 and
// float32 representations of a widened bool.
// ---------------------------------------------------------------------------
__global__ __launch_bounds__(256) void attn_kernel(const unsigned int* __restrict__ mask)
{
    extern __shared__ float sm[];
    float (*Qs)[68] = (float(*)[68])(sm);
    float (*Ks)[68] = (float(*)[68])(sm + 64 * 68);
    float (*Vt)[68] = (float(*)[68])(sm + 2 * 64 * 68);
    float (*Ps)[68] = (float(*)[68])(sm + 3 * 64 * 68);

    const int tid = threadIdx.x;
    const int ty = tid >> 4;
    const int tx = tid & 15;
    const int bh = blockIdx.y;
    const int b  = bh >> 4;
    const int h  = bh & 15;
    const int qbase = blockIdx.x * 64;

    const float slope = exp2f(-0.5f * (float)(h + 1));
    const float scale = 0.125f;  // 1/sqrt(64)

    const float* qptr = g_q + (size_t)bh * S_LEN * HDIM;
    const float* kptr = g_k + (size_t)bh * S_LEN * HDIM;
    const float* vptr = g_v + (size_t)bh * S_LEN * HDIM;
    const unsigned int* mrow = mask + (size_t)b * S_LEN;

    // Load Q tile once
#pragma unroll
    for (int r = 0; r < 4; r++) {
        int idx = tid + 256 * r;
        int row = idx >> 4;
        int c4  = (idx & 15) * 4;
        *(float4*)&Qs[row][c4] = *(const float4*)&qptr[(qbase + row) * HDIM + c4];
    }

    float m_i[4], l_i[4], o[4][4];
#pragma unroll
    for (int i = 0; i < 4; i++) {
        m_i[i] = -1e30f; l_i[i] = 0.f;
#pragma unroll
        for (int j = 0; j < 4; j++) o[i][j] = 0.f;
    }

    for (int kt = 0; kt < S_LEN / 64; kt++) {
        const int kbase = kt * 64;

        // Load K tile (row-major) and V tile transposed (Vt[d][k])
#pragma unroll
        for (int r = 0; r < 4; r++) {
            int idx = tid + 256 * r;
            int row = idx >> 4;
            int c4  = (idx & 15) * 4;
            *(float4*)&Ks[row][c4] = *(const float4*)&kptr[(kbase + row) * HDIM + c4];
        }
#pragma unroll
        for (int r = 0; r < 4; r++) {
            int idx = tid + 256 * r;
            int db = idx >> 6;        // 0..15 (d block of 4)
            int kl = idx & 63;        // key row in tile
            float4 v = *(const float4*)&vptr[(kbase + kl) * HDIM + 4 * db];
            Vt[4 * db + 0][kl] = v.x;
            Vt[4 * db + 1][kl] = v.y;
            Vt[4 * db + 2][kl] = v.z;
            Vt[4 * db + 3][kl] = v.w;
        }
        __syncthreads();

        // GEMM1: s = Q K^T
        float s[4][4] = {};
#pragma unroll
        for (int kk = 0; kk < 64; kk += 4) {
            float4 q4[4], k4[4];
#pragma unroll
            for (int i = 0; i < 4; i++) q4[i] = *(const float4*)&Qs[ty + 16 * i][kk];
#pragma unroll
            for (int j = 0; j < 4; j++) k4[j] = *(const float4*)&Ks[tx + 16 * j][kk];
#pragma unroll
            for (int i = 0; i < 4; i++)
#pragma unroll
                for (int j = 0; j < 4; j++) {
                    s[i][j] += q4[i].x * k4[j].x + q4[i].y * k4[j].y
                             + q4[i].z * k4[j].z + q4[i].w * k4[j].w;
                }
        }

        // Bias + mask (mask word nonzero => attend)
        int mok[4];
#pragma unroll
        for (int j = 0; j < 4; j++) mok[j] = (mrow[kbase + tx + 16 * j] != 0u) ? 1 : 0;
#pragma unroll
        for (int i = 0; i < 4; i++) {
            float qpos = (float)(qbase + ty + 16 * i);
#pragma unroll
            for (int j = 0; j < 4; j++) {
                float kpos = (float)(kbase + tx + 16 * j);
                float sv = s[i][j] * scale - slope * fabsf(kpos - qpos);
                if (!mok[j]) sv = -1e30f;
                s[i][j] = sv;
            }
        }

        // Online softmax (row reduction across 16-lane tx groups)
#pragma unroll
        for (int i = 0; i < 4; i++) {
            float rm = fmaxf(fmaxf(s[i][0], s[i][1]), fmaxf(s[i][2], s[i][3]));
#pragma unroll
            for (int d = 8; d >= 1; d >>= 1)
                rm = fmaxf(rm, __shfl_xor_sync(0xffffffffu, rm, d));
            float mnew = fmaxf(m_i[i], rm);
            float alpha = __expf(m_i[i] - mnew);
            float rs = 0.f;
#pragma unroll
            for (int j = 0; j < 4; j++) {
                float p = __expf(s[i][j] - mnew);
                s[i][j] = p;
                rs += p;
            }
#pragma unroll
            for (int d = 8; d >= 1; d >>= 1)
                rs += __shfl_xor_sync(0xffffffffu, rs, d);
            l_i[i] = l_i[i] * alpha + rs;
            m_i[i] = mnew;
#pragma unroll
            for (int j = 0; j < 4; j++) o[i][j] *= alpha;
            // stash P
#pragma unroll
            for (int j = 0; j < 4; j++) Ps[ty + 16 * i][tx + 16 * j] = s[i][j];
        }
        __syncthreads();

        // GEMM2: O += P V   (Vt[d][k] so contiguous-k dot)
#pragma unroll
        for (int kk = 0; kk < 64; kk += 4) {
            float4 p4[4], v4[4];
#pragma unroll
            for (int i = 0; i < 4; i++) p4[i] = *(const float4*)&Ps[ty + 16 * i][kk];
#pragma unroll
            for (int j = 0; j < 4; j++) v4[j] = *(const float4*)&Vt[tx + 16 * j][kk];
#pragma unroll
            for (int i = 0; i < 4; i++)
#pragma unroll
                for (int j = 0; j < 4; j++) {
                    o[i][j] += p4[i].x * v4[j].x + p4[i].y * v4[j].y
                             + p4[i].z * v4[j].z + p4[i].w * v4[j].w;
                }
        }
        __syncthreads();
    }

    // Finalize: divide by l, write [b, s, h*64+d]
#pragma unroll
    for (int i = 0; i < 4; i++) {
        int srow = qbase + ty + 16 * i;
        float inv = 1.f / l_i[i];
#pragma unroll
        for (int j = 0; j < 4; j++) {
            int d = tx + 16 * j;
            g_attn[((size_t)b * S_LEN + srow) * K_DIM + h * HDIM + d] = o[i][j] * inv;
        }
    }
}

// ---------------------------------------------------------------------------
extern "C" void kernel_launch(void* const* d_in, const int* in_sizes, int n_in,
                              void* d_out, int out_size)
{
    const float* x      = (const float*)d_in[0];
    const unsigned int* mask = (const unsigned int*)d_in[1];
    const float* qkv_w  = (const float*)d_in[2];
    const float* qkv_b  = (const float*)d_in[3];
    const float* out_w  = (const float*)d_in[4];
    const float* out_b  = (const float*)d_in[5];
    float* out = (float*)d_out;

    void* attn_ptr = nullptr;
    cudaGetSymbolAddress(&attn_ptr, g_attn);

    const int attn_smem = 4 * 64 * 68 * (int)sizeof(float);  // 69632 B
    cudaFuncSetAttribute(attn_kernel, cudaFuncAttributeMaxDynamicSharedMemorySize, attn_smem);

    // 1) QKV projection: [4096, 3072]
    dim3 g1(3072 / 64, 4096 / 64);
    gemm_nt_kernel<<<g1, 256>>>(x, qkv_w, qkv_b, nullptr, 3072, 1);

    // 2) Attention
    dim3 g2(S_LEN / 64, BH);
    attn_kernel<<<g2, 256, attn_smem>>>(mask);

    // 3) Output projection: [4096, 1024]
    dim3 g3(1024 / 64, 4096 / 64);
    gemm_nt_kernel<<<g3, 256>>>((const float*)attn_ptr, out_w, out_b, out, 1024, 0);
}

// round 6
// speedup vs baseline: 1.4562x; 1.4562x over previous
#include <cuda_runtime.h>
#include <cstdint>
#include <math.h>

#define K_DIM   1024
#define S_LEN   2048
#define BATCH   2
#define NHEADS  16
#define HDIM    64
#define BH      (BATCH*NHEADS)

// GEMM tiling
#define TILE_M  128
#define TILE_N  128
#define TILE_K  32
#define LDS_ROW 36                      // 32 + 4 pad floats; 144B row (16B aligned)
#define STG_F   (128*LDS_ROW)           // floats per stage per matrix = 4608
#define STG_B   (STG_F*4)               // 18432 bytes
#define GEMM_DSMEM (4*STG_B)            // A[2] + B[2] = 73728 B

// Scratch (device globals: no allocation allowed)
__device__ float g_q[BH * S_LEN * HDIM];
__device__ float g_k[BH * S_LEN * HDIM];
__device__ float g_v[BH * S_LEN * HDIM];
__device__ float g_attn[BATCH * S_LEN * K_DIM];
__device__ float g_xc[BATCH * S_LEN * K_DIM];     // tf32-rounded x
__device__ float g_wq[3 * K_DIM * K_DIM];         // tf32-rounded qkv_w
__device__ float g_wo[K_DIM * K_DIM];             // tf32-rounded out_w

// ---------------------------------------------------------------------------
__device__ __forceinline__ uint32_t s2u(const void* p) {
    uint32_t a;
    asm("{ .reg .u64 t; cvta.to.shared.u64 t, %1; cvt.u32.u64 %0, t; }" : "=r"(a) : "l"(p));
    return a;
}
#define CP16(dst, src) \
    asm volatile("cp.async.cg.shared.global [%0], [%1], 16;" :: "r"(dst), "l"(src) : "memory")
#define CP_COMMIT() asm volatile("cp.async.commit_group;" ::: "memory")
#define CP_WAIT1()  asm volatile("cp.async.wait_group 1;" ::: "memory")
#define CP_WAIT0()  asm volatile("cp.async.wait_group 0;" ::: "memory")

// m16n8k8 tf32 mma: D = A*B + D (fp32 accum)
#define MMA_TF32(c, a, b) \
    asm volatile("mma.sync.aligned.m16n8k8.row.col.f32.tf32.tf32.f32 " \
        "{%0,%1,%2,%3}, {%4,%5,%6,%7}, {%8,%9}, {%0,%1,%2,%3};" \
        : "+f"((c)[0]), "+f"((c)[1]), "+f"((c)[2]), "+f"((c)[3]) \
        : "r"((a)[0]), "r"((a)[1]), "r"((a)[2]), "r"((a)[3]), \
          "r"((b)[0]), "r"((b)[1]))

// tf32 RN pre-rounding (dest of cvt.*.tf32.f32 must be .b32)
__device__ __forceinline__ float tf32r(float v) {
    uint32_t r; asm("cvt.rna.tf32.f32 %0, %1;" : "=r"(r) : "f"(v));
    return __uint_as_float(r);
}
__global__ void cvt_tf32_kernel(const float4* __restrict__ in, float4* __restrict__ out, int n4) {
    int i = blockIdx.x * 256 + threadIdx.x;
    if (i < n4) {
        float4 v = in[i];
        v.x = tf32r(v.x); v.y = tf32r(v.y); v.z = tf32r(v.z); v.w = tf32r(v.w);
        out[i] = v;
    }
}

// ---------------------------------------------------------------------------
// Tensor-core NT GEMM via mma.sync tf32: C[m,n] = sum_k A[m,k]*W[n,k] + bias[n]
// 128x128 tile, 256 threads (8 warps, 4x2), warp tile 32x64 (2x8 m16n8k8).
// Double-buffered cp.async. mode 0: row-major C; mode 1: QKV scatter.
// ---------------------------------------------------------------------------
__global__ __launch_bounds__(256, 1) void gemm_mma_kernel(
    const float* __restrict__ A, const float* __restrict__ W,
    const float* __restrict__ bias, float* __restrict__ C,
    int N, int mode)
{
    extern __shared__ float sf[];
    float* sA = sf;                // [2][128][36]
    float* sB = sf + 2 * STG_F;

    const int tid  = threadIdx.x;
    const int wid  = tid >> 5;
    const int lane = tid & 31;
    const int wm = wid >> 1;       // 0..3 -> M offset wm*32
    const int wn = wid & 1;        // 0..1 -> N offset wn*64
    const int gq = lane >> 2;      // group id 0..7
    const int gt = lane & 3;       // thread-in-group 0..3
    const int mbase = blockIdx.y * TILE_M;
    const int nbase = blockIdx.x * TILE_N;

    const uint32_t sa_u = s2u(sA);
    const uint32_t sb_u = s2u(sB);

    // Per-thread cp.async slots: 4 x 16B per matrix per stage
    const float* pa[4]; const float* pb[4]; uint32_t da[4], db[4];
#pragma unroll
    for (int i = 0; i < 4; i++) {
        int slot = i * 256 + tid;      // 0..1023
        int row = slot >> 3;           // 0..127
        int c   = slot & 7;            // 16B chunk in row
        pa[i] = A + (size_t)(mbase + row) * K_DIM + c * 4;
        pb[i] = W + (size_t)(nbase + row) * K_DIM + c * 4;
        da[i] = sa_u + row * (LDS_ROW * 4) + c * 16;
        db[i] = sb_u + row * (LDS_ROW * 4) + c * 16;
    }

#define LOAD_STAGE(st, kc) do {                                   \
        uint32_t so = (uint32_t)(st) * STG_B;                     \
        int ko = (kc) * TILE_K;                                   \
        _Pragma("unroll")                                         \
        for (int i = 0; i < 4; i++) {                             \
            CP16(da[i] + so, pa[i] + ko);                         \
            CP16(db[i] + so, pb[i] + ko);                         \
        }                                                         \
        CP_COMMIT();                                              \
    } while (0)

    float acc[2][8][4];
#pragma unroll
    for (int mt = 0; mt < 2; mt++)
#pragma unroll
        for (int nt = 0; nt < 8; nt++)
#pragma unroll
            for (int r = 0; r < 4; r++) acc[mt][nt][r] = 0.f;

    LOAD_STAGE(0, 0);

    const int NCH = K_DIM / TILE_K;   // 32
    for (int kc = 0; kc < NCH; kc++) {
        if (kc + 1 < NCH) { LOAD_STAGE((kc + 1) & 1, kc + 1); CP_WAIT1(); }
        else              { CP_WAIT0(); }
        __syncthreads();

        const float* Ab = sA + (kc & 1) * STG_F;
        const float* Bb = sB + (kc & 1) * STG_F;

#pragma unroll
        for (int k8 = 0; k8 < TILE_K; k8 += 8) {
            uint32_t a[2][4], b[8][2];
#pragma unroll
            for (int mt = 0; mt < 2; mt++) {
                int r0 = wm * 32 + mt * 16 + gq;
                a[mt][0] = __float_as_uint(Ab[r0 * LDS_ROW + k8 + gt]);
                a[mt][1] = __float_as_uint(Ab[(r0 + 8) * LDS_ROW + k8 + gt]);
                a[mt][2] = __float_as_uint(Ab[r0 * LDS_ROW + k8 + 4 + gt]);
                a[mt][3] = __float_as_uint(Ab[(r0 + 8) * LDS_ROW + k8 + 4 + gt]);
            }
#pragma unroll
            for (int nt = 0; nt < 8; nt++) {
                int cn = wn * 64 + nt * 8 + gq;
                b[nt][0] = __float_as_uint(Bb[cn * LDS_ROW + k8 + gt]);
                b[nt][1] = __float_as_uint(Bb[cn * LDS_ROW + k8 + 4 + gt]);
            }
#pragma unroll
            for (int mt = 0; mt < 2; mt++)
#pragma unroll
                for (int nt = 0; nt < 8; nt++)
                    MMA_TF32(acc[mt][nt], a[mt], b[nt]);
        }
        __syncthreads();
    }

    // Epilogue: c0/c1 at (row, col..col+1), c2/c3 at (row+8, same cols)
#pragma unroll
    for (int mt = 0; mt < 2; mt++) {
#pragma unroll
        for (int nt = 0; nt < 8; nt++) {
            int m0 = mbase + wm * 32 + mt * 16 + gq;
            int n0 = nbase + wn * 64 + nt * 8 + 2 * gt;
            float b0 = bias[n0], b1 = bias[n0 + 1];
            float v0 = acc[mt][nt][0] + b0, v1 = acc[mt][nt][1] + b1;
            float v2 = acc[mt][nt][2] + b0, v3 = acc[mt][nt][3] + b1;
            if (mode == 0) {
                *(float2*)&C[(size_t)m0 * N + n0]       = make_float2(v0, v1);
                *(float2*)&C[(size_t)(m0 + 8) * N + n0] = make_float2(v2, v3);
            } else {
                int part = n0 >> 10, nn = n0 & 1023;
                int h = nn >> 6, d = nn & 63;
                float* buf = (part == 0) ? g_q : (part == 1) ? g_k : g_v;
                int b_ = m0 >> 11, s0 = m0 & 2047;
                size_t base = (((size_t)(b_ * NHEADS + h)) * S_LEN);
                *(float2*)&buf[(base + s0) * HDIM + d]     = make_float2(v0, v1);
                *(float2*)&buf[(base + s0 + 8) * HDIM + d] = make_float2(v2, v3);
            }
        }
    }
}

// ---------------------------------------------------------------------------
// Flash-style ALiBi attention (unchanged; output tf32-rounded at store so the
// out-proj A operand is pre-rounded).
// ---------------------------------------------------------------------------
__global__ __launch_bounds__(256) void attn_kernel(const unsigned int* __restrict__ mask)
{
    extern __shared__ float sm[];
    float (*Qs)[68] = (float(*)[68])(sm);
    float (*Ks)[68] = (float(*)[68])(sm + 64 * 68);
    float (*Vt)[68] = (float(*)[68])(sm + 2 * 64 * 68);
    float (*Ps)[68] = (float(*)[68])(sm + 3 * 64 * 68);

    const int tid = threadIdx.x;
    const int ty = tid >> 4;
    const int tx = tid & 15;
    const int bh = blockIdx.y;
    const int b  = bh >> 4;
    const int h  = bh & 15;
    const int qbase = blockIdx.x * 64;

    const float slope = exp2f(-0.5f * (float)(h + 1));
    const float scale = 0.125f;

    const float* qptr = g_q + (size_t)bh * S_LEN * HDIM;
    const float* kptr = g_k + (size_t)bh * S_LEN * HDIM;
    const float* vptr = g_v + (size_t)bh * S_LEN * HDIM;
    const unsigned int* mrow = mask + (size_t)b * S_LEN;

#pragma unroll
    for (int r = 0; r < 4; r++) {
        int idx = tid + 256 * r;
        int row = idx >> 4;
        int c4  = (idx & 15) * 4;
        *(float4*)&Qs[row][c4] = *(const float4*)&qptr[(qbase + row) * HDIM + c4];
    }

    float m_i[4], l_i[4], o[4][4];
#pragma unroll
    for (int i = 0; i < 4; i++) {
        m_i[i] = -1e30f; l_i[i] = 0.f;
#pragma unroll
        for (int j = 0; j < 4; j++) o[i][j] = 0.f;
    }

    for (int kt = 0; kt < S_LEN / 64; kt++) {
        const int kbase = kt * 64;
#pragma unroll
        for (int r = 0; r < 4; r++) {
            int idx = tid + 256 * r;
            int row = idx >> 4;
            int c4  = (idx & 15) * 4;
            *(float4*)&Ks[row][c4] = *(const float4*)&kptr[(kbase + row) * HDIM + c4];
        }
#pragma unroll
        for (int r = 0; r < 4; r++) {
            int idx = tid + 256 * r;
            int db = idx >> 6;
            int kl = idx & 63;
            float4 v = *(const float4*)&vptr[(kbase + kl) * HDIM + 4 * db];
            Vt[4 * db + 0][kl] = v.x;
            Vt[4 * db + 1][kl] = v.y;
            Vt[4 * db + 2][kl] = v.z;
            Vt[4 * db + 3][kl] = v.w;
        }
        __syncthreads();

        float s[4][4] = {};
#pragma unroll
        for (int kk = 0; kk < 64; kk += 4) {
            float4 q4[4], k4[4];
#pragma unroll
            for (int i = 0; i < 4; i++) q4[i] = *(const float4*)&Qs[ty + 16 * i][kk];
#pragma unroll
            for (int j = 0; j < 4; j++) k4[j] = *(const float4*)&Ks[tx + 16 * j][kk];
#pragma unroll
            for (int i = 0; i < 4; i++)
#pragma unroll
                for (int j = 0; j < 4; j++) {
                    s[i][j] += q4[i].x * k4[j].x + q4[i].y * k4[j].y
                             + q4[i].z * k4[j].z + q4[i].w * k4[j].w;
                }
        }

        int mok[4];
#pragma unroll
        for (int j = 0; j < 4; j++) mok[j] = (mrow[kbase + tx + 16 * j] != 0u) ? 1 : 0;
#pragma unroll
        for (int i = 0; i < 4; i++) {
            float qpos = (float)(qbase + ty + 16 * i);
#pragma unroll
            for (int j = 0; j < 4; j++) {
                float kpos = (float)(kbase + tx + 16 * j);
                float sv = s[i][j] * scale - slope * fabsf(kpos - qpos);
                if (!mok[j]) sv = -1e30f;
                s[i][j] = sv;
            }
        }

#pragma unroll
        for (int i = 0; i < 4; i++) {
            float rm = fmaxf(fmaxf(s[i][0], s[i][1]), fmaxf(s[i][2], s[i][3]));
#pragma unroll
            for (int d = 8; d >= 1; d >>= 1)
                rm = fmaxf(rm, __shfl_xor_sync(0xffffffffu, rm, d));
            float mnew = fmaxf(m_i[i], rm);
            float alpha = __expf(m_i[i] - mnew);
            float rs = 0.f;
#pragma unroll
            for (int j = 0; j < 4; j++) {
                float p = __expf(s[i][j] - mnew);
                s[i][j] = p;
                rs += p;
            }
#pragma unroll
            for (int d = 8; d >= 1; d >>= 1)
                rs += __shfl_xor_sync(0xffffffffu, rs, d);
            l_i[i] = l_i[i] * alpha + rs;
            m_i[i] = mnew;
#pragma unroll
            for (int j = 0; j < 4; j++) o[i][j] *= alpha;
#pragma unroll
            for (int j = 0; j < 4; j++) Ps[ty + 16 * i][tx + 16 * j] = s[i][j];
        }
        __syncthreads();

#pragma unroll
        for (int kk = 0; kk < 64; kk += 4) {
            float4 p4[4], v4[4];
#pragma unroll
            for (int i = 0; i < 4; i++) p4[i] = *(const float4*)&Ps[ty + 16 * i][kk];
#pragma unroll
            for (int j = 0; j < 4; j++) v4[j] = *(const float4*)&Vt[tx + 16 * j][kk];
#pragma unroll
            for (int i = 0; i < 4; i++)
#pragma unroll
                for (int j = 0; j < 4; j++) {
                    o[i][j] += p4[i].x * v4[j].x + p4[i].y * v4[j].y
                             + p4[i].z * v4[j].z + p4[i].w * v4[j].w;
                }
        }
        __syncthreads();
    }

#pragma unroll
    for (int i = 0; i < 4; i++) {
        int srow = qbase + ty + 16 * i;
        float inv = 1.f / l_i[i];
#pragma unroll
        for (int j = 0; j < 4; j++) {
            int d = tx + 16 * j;
            g_attn[((size_t)b * S_LEN + srow) * K_DIM + h * HDIM + d] = tf32r(o[i][j] * inv);
        }
    }
}

// ---------------------------------------------------------------------------
extern "C" void kernel_launch(void* const* d_in, const int* in_sizes, int n_in,
                              void* d_out, int out_size)
{
    const float* x      = (const float*)d_in[0];
    const unsigned int* mask = (const unsigned int*)d_in[1];
    const float* qkv_w  = (const float*)d_in[2];
    const float* qkv_b  = (const float*)d_in[3];
    const float* out_w  = (const float*)d_in[4];
    const float* out_b  = (const float*)d_in[5];
    float* out = (float*)d_out;

    void *p_attn, *p_xc, *p_wq, *p_wo;
    cudaGetSymbolAddress(&p_attn, g_attn);
    cudaGetSymbolAddress(&p_xc, g_xc);
    cudaGetSymbolAddress(&p_wq, g_wq);
    cudaGetSymbolAddress(&p_wo, g_wo);

    const int attn_smem = 4 * 64 * 68 * (int)sizeof(float);
    cudaFuncSetAttribute(attn_kernel, cudaFuncAttributeMaxDynamicSharedMemorySize, attn_smem);
    cudaFuncSetAttribute(gemm_mma_kernel, cudaFuncAttributeMaxDynamicSharedMemorySize, GEMM_DSMEM);

    // 0) tf32-round inputs
    {
        int n4 = BATCH * S_LEN * K_DIM / 4;
        cvt_tf32_kernel<<<(n4 + 255) / 256, 256>>>((const float4*)x, (float4*)p_xc, n4);
        n4 = 3 * K_DIM * K_DIM / 4;
        cvt_tf32_kernel<<<(n4 + 255) / 256, 256>>>((const float4*)qkv_w, (float4*)p_wq, n4);
        n4 = K_DIM * K_DIM / 4;
        cvt_tf32_kernel<<<(n4 + 255) / 256, 256>>>((const float4*)out_w, (float4*)p_wo, n4);
    }

    // 1) QKV projection [4096 x 3072] (mma.sync tf32)
    dim3 g1(3 * K_DIM / TILE_N, BATCH * S_LEN / TILE_M);
    gemm_mma_kernel<<<g1, 256, GEMM_DSMEM>>>((const float*)p_xc, (const float*)p_wq,
                                             qkv_b, nullptr, 3 * K_DIM, 1);

    // 2) Attention
    dim3 g2(S_LEN / 64, BH);
    attn_kernel<<<g2, 256, attn_smem>>>(mask);

    // 3) Output projection [4096 x 1024] (mma.sync tf32)
    dim3 g3(K_DIM / TILE_N, BATCH * S_LEN / TILE_M);
    gemm_mma_kernel<<<g3, 256, GEMM_DSMEM>>>((const float*)p_attn, (const float*)p_wo,
                                             out_b, out, K_DIM, 0);
}

// round 7
// speedup vs baseline: 3.0926x; 2.1237x over previous
#include <cuda_runtime.h>
#include <cstdint>
#include <math.h>

#define K_DIM   1024
#define S_LEN   2048
#define BATCH   2
#define NHEADS  16
#define HDIM    64
#define BH      (BATCH*NHEADS)

// GEMM tiling
#define TILE_M  128
#define TILE_N  128
#define TILE_K  32
#define LDS_ROW 36
#define STG_F   (128*LDS_ROW)
#define STG_B   (STG_F*4)
#define GEMM_DSMEM (4*STG_B)

// Attention tiling
#define AQT 128
#define AKT 64
#define ANT (S_LEN/AKT)            // 32 key tiles
// smem float offsets
#define A_QP  0                    // [128][68] Q then P
#define A_KS  8704                 // [2][64][68]
#define A_VS  17408                // [2][64][72]
#define A_MK  26624                // [2][64]
#define ATTN_DSMEM ((26624 + 128) * 4)   // 107008 B

// Scratch (device globals: no allocation allowed)
__device__ float g_q[BH * S_LEN * HDIM];
__device__ float g_k[BH * S_LEN * HDIM];
__device__ float g_v[BH * S_LEN * HDIM];
__device__ float g_attn[BATCH * S_LEN * K_DIM];
__device__ float g_xc[BATCH * S_LEN * K_DIM];
__device__ float g_wq[3 * K_DIM * K_DIM];
__device__ float g_wo[K_DIM * K_DIM];

// ---------------------------------------------------------------------------
__device__ __forceinline__ uint32_t s2u(const void* p) {
    uint32_t a;
    asm("{ .reg .u64 t; cvta.to.shared.u64 t, %1; cvt.u32.u64 %0, t; }" : "=r"(a) : "l"(p));
    return a;
}
#define CP16(dst, src) \
    asm volatile("cp.async.cg.shared.global [%0], [%1], 16;" :: "r"(dst), "l"(src) : "memory")
#define CP_COMMIT() asm volatile("cp.async.commit_group;" ::: "memory")
#define CP_WAIT1()  asm volatile("cp.async.wait_group 1;" ::: "memory")
#define CP_WAIT0()  asm volatile("cp.async.wait_group 0;" ::: "memory")

#define MMA_TF32(c, a, b) \
    asm volatile("mma.sync.aligned.m16n8k8.row.col.f32.tf32.tf32.f32 " \
        "{%0,%1,%2,%3}, {%4,%5,%6,%7}, {%8,%9}, {%0,%1,%2,%3};" \
        : "+f"((c)[0]), "+f"((c)[1]), "+f"((c)[2]), "+f"((c)[3]) \
        : "r"((a)[0]), "r"((a)[1]), "r"((a)[2]), "r"((a)[3]), \
          "r"((b)[0]), "r"((b)[1]))

__device__ __forceinline__ float tf32r(float v) {
    uint32_t r; asm("cvt.rna.tf32.f32 %0, %1;" : "=r"(r) : "f"(v));
    return __uint_as_float(r);
}
__global__ void cvt_tf32_kernel(const float4* __restrict__ in, float4* __restrict__ out, int n4) {
    int i = blockIdx.x * 256 + threadIdx.x;
    if (i < n4) {
        float4 v = in[i];
        v.x = tf32r(v.x); v.y = tf32r(v.y); v.z = tf32r(v.z); v.w = tf32r(v.w);
        out[i] = v;
    }
}

// ---------------------------------------------------------------------------
// Tensor-core NT GEMM (validated in round 6). mode 1 now tf32-rounds its
// outputs so attention's mma consumes round-to-nearest operands.
// ---------------------------------------------------------------------------
__global__ __launch_bounds__(256, 1) void gemm_mma_kernel(
    const float* __restrict__ A, const float* __restrict__ W,
    const float* __restrict__ bias, float* __restrict__ C,
    int N, int mode)
{
    extern __shared__ float sf[];
    float* sA = sf;
    float* sB = sf + 2 * STG_F;

    const int tid  = threadIdx.x;
    const int wid  = tid >> 5;
    const int lane = tid & 31;
    const int wm = wid >> 1;
    const int wn = wid & 1;
    const int gq = lane >> 2;
    const int gt = lane & 3;
    const int mbase = blockIdx.y * TILE_M;
    const int nbase = blockIdx.x * TILE_N;

    const uint32_t sa_u = s2u(sA);
    const uint32_t sb_u = s2u(sB);

    const float* pa[4]; const float* pb[4]; uint32_t da[4], db[4];
#pragma unroll
    for (int i = 0; i < 4; i++) {
        int slot = i * 256 + tid;
        int row = slot >> 3;
        int c   = slot & 7;
        pa[i] = A + (size_t)(mbase + row) * K_DIM + c * 4;
        pb[i] = W + (size_t)(nbase + row) * K_DIM + c * 4;
        da[i] = sa_u + row * (LDS_ROW * 4) + c * 16;
        db[i] = sb_u + row * (LDS_ROW * 4) + c * 16;
    }

#define LOAD_STAGE(st, kc) do {                                   \
        uint32_t so = (uint32_t)(st) * STG_B;                     \
        int ko = (kc) * TILE_K;                                   \
        _Pragma("unroll")                                         \
        for (int i = 0; i < 4; i++) {                             \
            CP16(da[i] + so, pa[i] + ko);                         \
            CP16(db[i] + so, pb[i] + ko);                         \
        }                                                         \
        CP_COMMIT();                                              \
    } while (0)

    float acc[2][8][4];
#pragma unroll
    for (int mt = 0; mt < 2; mt++)
#pragma unroll
        for (int nt = 0; nt < 8; nt++)
#pragma unroll
            for (int r = 0; r < 4; r++) acc[mt][nt][r] = 0.f;

    LOAD_STAGE(0, 0);

    const int NCH = K_DIM / TILE_K;
    for (int kc = 0; kc < NCH; kc++) {
        if (kc + 1 < NCH) { LOAD_STAGE((kc + 1) & 1, kc + 1); CP_WAIT1(); }
        else              { CP_WAIT0(); }
        __syncthreads();

        const float* Ab = sA + (kc & 1) * STG_F;
        const float* Bb = sB + (kc & 1) * STG_F;

#pragma unroll
        for (int k8 = 0; k8 < TILE_K; k8 += 8) {
            uint32_t a[2][4], b[8][2];
#pragma unroll
            for (int mt = 0; mt < 2; mt++) {
                int r0 = wm * 32 + mt * 16 + gq;
                a[mt][0] = __float_as_uint(Ab[r0 * LDS_ROW + k8 + gt]);
                a[mt][1] = __float_as_uint(Ab[(r0 + 8) * LDS_ROW + k8 + gt]);
                a[mt][2] = __float_as_uint(Ab[r0 * LDS_ROW + k8 + 4 + gt]);
                a[mt][3] = __float_as_uint(Ab[(r0 + 8) * LDS_ROW + k8 + 4 + gt]);
            }
#pragma unroll
            for (int nt = 0; nt < 8; nt++) {
                int cn = wn * 64 + nt * 8 + gq;
                b[nt][0] = __float_as_uint(Bb[cn * LDS_ROW + k8 + gt]);
                b[nt][1] = __float_as_uint(Bb[cn * LDS_ROW + k8 + 4 + gt]);
            }
#pragma unroll
            for (int mt = 0; mt < 2; mt++)
#pragma unroll
                for (int nt = 0; nt < 8; nt++)
                    MMA_TF32(acc[mt][nt], a[mt], b[nt]);
        }
        __syncthreads();
    }

#pragma unroll
    for (int mt = 0; mt < 2; mt++) {
#pragma unroll
        for (int nt = 0; nt < 8; nt++) {
            int m0 = mbase + wm * 32 + mt * 16 + gq;
            int n0 = nbase + wn * 64 + nt * 8 + 2 * gt;
            float b0 = bias[n0], b1 = bias[n0 + 1];
            float v0 = acc[mt][nt][0] + b0, v1 = acc[mt][nt][1] + b1;
            float v2 = acc[mt][nt][2] + b0, v3 = acc[mt][nt][3] + b1;
            if (mode == 0) {
                *(float2*)&C[(size_t)m0 * N + n0]       = make_float2(v0, v1);
                *(float2*)&C[(size_t)(m0 + 8) * N + n0] = make_float2(v2, v3);
            } else {
                int part = n0 >> 10, nn = n0 & 1023;
                int h = nn >> 6, d = nn & 63;
                float* buf = (part == 0) ? g_q : (part == 1) ? g_k : g_v;
                int b_ = m0 >> 11, s0 = m0 & 2047;
                size_t base = (((size_t)(b_ * NHEADS + h)) * S_LEN);
                *(float2*)&buf[(base + s0) * HDIM + d] =
                    make_float2(tf32r(v0), tf32r(v1));
                *(float2*)&buf[(base + s0 + 8) * HDIM + d] =
                    make_float2(tf32r(v2), tf32r(v3));
            }
        }
    }
}

// ---------------------------------------------------------------------------
// Flash ALiBi attention via mma.sync tf32.
// CTA: 256 thr / 8 warps, Q-tile 128 rows (16/warp), key tiles of 64,
// double-buffered cp.async K/V. Q fragments register-resident.
// P routed through per-warp-private smem (syncwarp only).
// ---------------------------------------------------------------------------
__global__ __launch_bounds__(256, 1) void attn_mma_kernel(const unsigned int* __restrict__ mask)
{
    extern __shared__ float sm[];
    float* QP = sm + A_QP;          // [128][68]
    float* KS = sm + A_KS;          // [2][64][68]
    float* VS = sm + A_VS;          // [2][64][72]
    float* MK = sm + A_MK;          // [2][64]

    const int tid = threadIdx.x;
    const int wid = tid >> 5;
    const int lane = tid & 31;
    const int gq = lane >> 2;
    const int gt = lane & 3;
    const int bh = blockIdx.y;
    const int b  = bh >> 4;
    const int h  = bh & 15;
    const int qbase = blockIdx.x * AQT;

    const float slope = exp2f(-0.5f * (float)(h + 1));
    const float scale = 0.125f;

    const float* qptr = g_q + (size_t)bh * S_LEN * HDIM;
    const float* kptr = g_k + (size_t)bh * S_LEN * HDIM;
    const float* vptr = g_v + (size_t)bh * S_LEN * HDIM;
    const unsigned int* mrow = mask + (size_t)b * S_LEN;

    const uint32_t ks_u = s2u(KS);
    const uint32_t vs_u = s2u(VS);

    // Load Q tile coalesced into smem
#pragma unroll
    for (int r = 0; r < 8; r++) {
        int idx = tid + 256 * r;
        int row = idx >> 4;
        int c4  = (idx & 15) * 4;
        *(float4*)&QP[row * 68 + c4] = *(const float4*)&qptr[(qbase + row) * HDIM + c4];
    }
    __syncthreads();

    // Extract Q fragments (row.major A for m16n8k8): reused across all key tiles
    const int r0 = wid * 16 + gq;           // warp-local row (and +8)
    uint32_t qf[8][4];
#pragma unroll
    for (int ki = 0; ki < 8; ki++) {
        int k = ki * 8;
        qf[ki][0] = __float_as_uint(QP[r0 * 68 + k + gt]);
        qf[ki][1] = __float_as_uint(QP[(r0 + 8) * 68 + k + gt]);
        qf[ki][2] = __float_as_uint(QP[r0 * 68 + k + 4 + gt]);
        qf[ki][3] = __float_as_uint(QP[(r0 + 8) * 68 + k + 4 + gt]);
    }
    __syncthreads();    // QP now repurposed as P buffer

    float m0 = -1e30f, m1 = -1e30f, l0 = 0.f, l1 = 0.f;
    float oacc[8][4];
#pragma unroll
    for (int nt = 0; nt < 8; nt++)
#pragma unroll
        for (int r = 0; r < 4; r++) oacc[nt][r] = 0.f;

#define LOADKV(st, kt_) do {                                                   \
        int kb_ = (kt_) * AKT;                                                 \
        uint32_t ko_ = ks_u + (uint32_t)(st) * (4352 * 4);                     \
        uint32_t vo_ = vs_u + (uint32_t)(st) * (4608 * 4);                     \
        _Pragma("unroll")                                                      \
        for (int i = 0; i < 4; i++) {                                          \
            int idx = tid + 256 * i;                                           \
            int row = idx >> 4;                                                \
            int c   = idx & 15;                                                \
            CP16(ko_ + (uint32_t)(row * 68 + c * 4) * 4,                       \
                 kptr + (size_t)(kb_ + row) * HDIM + c * 4);                   \
            CP16(vo_ + (uint32_t)(row * 72 + c * 4) * 4,                       \
                 vptr + (size_t)(kb_ + row) * HDIM + c * 4);                   \
        }                                                                      \
        CP_COMMIT();                                                           \
        if (tid < 64) MK[(st) * 64 + tid] = (mrow[kb_ + tid] != 0u) ? 0.f : -1e30f; \
    } while (0)

    LOADKV(0, 0);

    const float rowf0 = (float)(qbase + r0);
    const float rowf1 = (float)(qbase + r0 + 8);

    for (int kt = 0; kt < ANT; kt++) {
        if (kt + 1 < ANT) { LOADKV((kt + 1) & 1, kt + 1); CP_WAIT1(); }
        else              { CP_WAIT0(); }
        __syncthreads();

        const float* Kb = KS + (kt & 1) * 4352;
        const float* Vb = VS + (kt & 1) * 4608;
        const float* Mb = MK + (kt & 1) * 64;
        const int kbase = kt * AKT;

        // GEMM1: S = Q K^T  (warp 16 x 64)
        float sacc[8][4];
#pragma unroll
        for (int nt = 0; nt < 8; nt++)
#pragma unroll
            for (int r = 0; r < 4; r++) sacc[nt][r] = 0.f;
#pragma unroll
        for (int ki = 0; ki < 8; ki++) {
            int k = ki * 8;
            uint32_t bb[8][2];
#pragma unroll
            for (int nt = 0; nt < 8; nt++) {
                bb[nt][0] = __float_as_uint(Kb[(nt * 8 + gq) * 68 + k + gt]);
                bb[nt][1] = __float_as_uint(Kb[(nt * 8 + gq) * 68 + k + 4 + gt]);
            }
#pragma unroll
            for (int nt = 0; nt < 8; nt++)
                MMA_TF32(sacc[nt], qf[ki], bb[nt]);
        }

        // Bias + mask + online softmax (rows r0 via c0/c1, r0+8 via c2/c3)
        float rm0 = -1e30f, rm1 = -1e30f;
#pragma unroll
        for (int nt = 0; nt < 8; nt++) {
#pragma unroll
            for (int e = 0; e < 2; e++) {
                int cl = nt * 8 + 2 * gt + e;
                float colf = (float)(kbase + cl);
                float mk = Mb[cl];
                float v0 = sacc[nt][e]     * scale - slope * fabsf(colf - rowf0) + mk;
                float v1 = sacc[nt][2 + e] * scale - slope * fabsf(colf - rowf1) + mk;
                sacc[nt][e] = v0; sacc[nt][2 + e] = v1;
                rm0 = fmaxf(rm0, v0); rm1 = fmaxf(rm1, v1);
            }
        }
        rm0 = fmaxf(rm0, __shfl_xor_sync(0xffffffffu, rm0, 1));
        rm0 = fmaxf(rm0, __shfl_xor_sync(0xffffffffu, rm0, 2));
        rm1 = fmaxf(rm1, __shfl_xor_sync(0xffffffffu, rm1, 1));
        rm1 = fmaxf(rm1, __shfl_xor_sync(0xffffffffu, rm1, 2));

        float mn0 = fmaxf(m0, rm0), mn1 = fmaxf(m1, rm1);
        float al0 = __expf(m0 - mn0), al1 = __expf(m1 - mn1);
        float rs0 = 0.f, rs1 = 0.f;
#pragma unroll
        for (int nt = 0; nt < 8; nt++) {
#pragma unroll
            for (int e = 0; e < 2; e++) {
                float p0 = __expf(sacc[nt][e] - mn0);
                float p1 = __expf(sacc[nt][2 + e] - mn1);
                sacc[nt][e] = p0; sacc[nt][2 + e] = p1;
                rs0 += p0; rs1 += p1;
            }
        }
        rs0 += __shfl_xor_sync(0xffffffffu, rs0, 1);
        rs0 += __shfl_xor_sync(0xffffffffu, rs0, 2);
        rs1 += __shfl_xor_sync(0xffffffffu, rs1, 1);
        rs1 += __shfl_xor_sync(0xffffffffu, rs1, 2);
        l0 = l0 * al0 + rs0; l1 = l1 * al1 + rs1;
        m0 = mn0; m1 = mn1;
#pragma unroll
        for (int nt = 0; nt < 8; nt++) {
            oacc[nt][0] *= al0; oacc[nt][1] *= al0;
            oacc[nt][2] *= al1; oacc[nt][3] *= al1;
        }

        // Stash P (tf32-rounded) in per-warp-private smem region
        __syncwarp();
#pragma unroll
        for (int nt = 0; nt < 8; nt++) {
            *(float2*)&QP[r0 * 68 + nt * 8 + 2 * gt] =
                make_float2(tf32r(sacc[nt][0]), tf32r(sacc[nt][1]));
            *(float2*)&QP[(r0 + 8) * 68 + nt * 8 + 2 * gt] =
                make_float2(tf32r(sacc[nt][2]), tf32r(sacc[nt][3]));
        }
        __syncwarp();

        // GEMM2: O += P V  (K dim = 64 keys)
#pragma unroll
        for (int ki = 0; ki < 8; ki++) {
            int k = ki * 8;
            uint32_t a[4];
            a[0] = __float_as_uint(QP[r0 * 68 + k + gt]);
            a[1] = __float_as_uint(QP[(r0 + 8) * 68 + k + gt]);
            a[2] = __float_as_uint(QP[r0 * 68 + k + 4 + gt]);
            a[3] = __float_as_uint(QP[(r0 + 8) * 68 + k + 4 + gt]);
            uint32_t bb[8][2];
#pragma unroll
            for (int nt = 0; nt < 8; nt++) {
                bb[nt][0] = __float_as_uint(Vb[(k + gt) * 72 + nt * 8 + gq]);
                bb[nt][1] = __float_as_uint(Vb[(k + 4 + gt) * 72 + nt * 8 + gq]);
            }
#pragma unroll
            for (int nt = 0; nt < 8; nt++)
                MMA_TF32(oacc[nt], a, bb[nt]);
        }
        __syncthreads();   // protect K/V double buffers
    }

    // Epilogue: rows qbase+r0 and +8, cols h*64 + nt*8 + 2*gt
    float inv0 = 1.f / l0, inv1 = 1.f / l1;
    size_t orow0 = ((size_t)b * S_LEN + qbase + r0) * K_DIM + h * HDIM;
    size_t orow1 = orow0 + 8 * K_DIM;
#pragma unroll
    for (int nt = 0; nt < 8; nt++) {
        int c = nt * 8 + 2 * gt;
        *(float2*)&g_attn[orow0 + c] =
            make_float2(tf32r(oacc[nt][0] * inv0), tf32r(oacc[nt][1] * inv0));
        *(float2*)&g_attn[orow1 + c] =
            make_float2(tf32r(oacc[nt][2] * inv1), tf32r(oacc[nt][3] * inv1));
    }
}

// ---------------------------------------------------------------------------
extern "C" void kernel_launch(void* const* d_in, const int* in_sizes, int n_in,
                              void* d_out, int out_size)
{
    const float* x      = (const float*)d_in[0];
    const unsigned int* mask = (const unsigned int*)d_in[1];
    const float* qkv_w  = (const float*)d_in[2];
    const float* qkv_b  = (const float*)d_in[3];
    const float* out_w  = (const float*)d_in[4];
    const float* out_b  = (const float*)d_in[5];
    float* out = (float*)d_out;

    void *p_attn, *p_xc, *p_wq, *p_wo;
    cudaGetSymbolAddress(&p_attn, g_attn);
    cudaGetSymbolAddress(&p_xc, g_xc);
    cudaGetSymbolAddress(&p_wq, g_wq);
    cudaGetSymbolAddress(&p_wo, g_wo);

    cudaFuncSetAttribute(attn_mma_kernel, cudaFuncAttributeMaxDynamicSharedMemorySize, ATTN_DSMEM);
    cudaFuncSetAttribute(gemm_mma_kernel, cudaFuncAttributeMaxDynamicSharedMemorySize, GEMM_DSMEM);

    // 0) tf32-round inputs
    {
        int n4 = BATCH * S_LEN * K_DIM / 4;
        cvt_tf32_kernel<<<(n4 + 255) / 256, 256>>>((const float4*)x, (float4*)p_xc, n4);
        n4 = 3 * K_DIM * K_DIM / 4;
        cvt_tf32_kernel<<<(n4 + 255) / 256, 256>>>((const float4*)qkv_w, (float4*)p_wq, n4);
        n4 = K_DIM * K_DIM / 4;
        cvt_tf32_kernel<<<(n4 + 255) / 256, 256>>>((const float4*)out_w, (float4*)p_wo, n4);
    }

    // 1) QKV projection [4096 x 3072]
    dim3 g1(3 * K_DIM / TILE_N, BATCH * S_LEN / TILE_M);
    gemm_mma_kernel<<<g1, 256, GEMM_DSMEM>>>((const float*)p_xc, (const float*)p_wq,
                                             qkv_b, nullptr, 3 * K_DIM, 1);

    // 2) Attention (mma.sync)
    dim3 g2(S_LEN / AQT, BH);
    attn_mma_kernel<<<g2, 256, ATTN_DSMEM>>>(mask);

    // 3) Output projection [4096 x 1024]
    dim3 g3(K_DIM / TILE_N, BATCH * S_LEN / TILE_M);
    gemm_mma_kernel<<<g3, 256, GEMM_DSMEM>>>((const float*)p_attn, (const float*)p_wo,
                                             out_b, out, K_DIM, 0);
}